// round 14
// baseline (speedup 1.0000x reference)
#include <cuda_runtime.h>
#include <cuda_fp16.h>
#include <mma.h>
#include <math.h>
#include <stdint.h>

using namespace nvcuda;

// ================= problem constants =================
#define NODES   32768
#define CTA_M   128
#define THREADS 256
#define DOUT    240
#define KTOT    2624            // 2080 ss + 528 vv + 16 pad = 41*64
#define KCH0    41
#define NPAIR2  528
#define PGRPS   33              // 528/16

// ================= smem layout =================
#define LD       136            // halves
#define WB_LD    72             // halves
#define YS_LD    132            // floats (GEMM2 col-major staging)
#define Y1_LD    68             // floats (GEMM1 row-major staging)

#define OFF_ST   0              // sT[64][136]  half  17408
#define OFF_VT   17408          // vT[96][136]  half  26112
#define OFF_C    43520          // union region       53248
#define SMEM_TOTAL 96768

// region C sub-layouts (phase-exclusive)
#define C_XT0   (OFF_C)             // GEMM0 X tile buf0   17408
#define C_XT1   (OFF_C + 17408)     //              buf1   17408
#define C_WB0   (OFF_C + 34816)     // GEMM0 W tile buf0    9216
#define C_WB1   (OFF_C + 44032)     //              buf1    9216
#define C1_YS   (OFF_C)             // GEMM1 staging (row-major 128x68 f) 34816
#define C2_XT0  (OFF_C)             // GEMM2 feat buf0     21760
#define C2_XT1  (OFF_C + 21760)     //            buf1     21760
#define C2_YS   (OFF_C)             // GEMM2 staging (post-loop) 42240

struct alignas(16) H8 { __half2 h[4]; };

// ================= preprocessed weights (gmem) =================
__device__ __half d_Wcat[KTOT * 64];        // [k][p]
__device__ __half d_Wc1 [64 * 1024];        // [u][q*32+v]
__device__ __half d_Wc2 [PGRPS * 80 * 16];  // [(pg*80 + m*16 + pi)][r]
__device__ unsigned short d_pairs [KTOT];
__device__ unsigned short d_pairs2[NPAIR2];
__device__ float d_g[32];

#define N_CAT (KTOT * 64)
#define B_C1  N_CAT
#define N_C1  (64 * 1024)
#define B_C2  (B_C1 + N_C1)
#define N_C2  (PGRPS * 80 * 16)
#define B_PR  (B_C2 + N_C2)
#define B_PR2 (B_PR + KTOT)
#define B_G   (B_PR2 + NPAIR2)
#define N_ALL (B_G + 32)

// ================= prep kernel =================
__device__ __forceinline__ void pair_decode(int k, int width, int& u, int& v) {
    int uu = 0, rem = k;
    while (rem >= width - uu) { rem -= width - uu; uu++; }
    u = uu; v = uu + rem;
}

__global__ void prep_all(const float* __restrict__ gates, const float* __restrict__ Wss0,
                         const float* __restrict__ Wsv1, const float* __restrict__ Wvv0,
                         const float* __restrict__ Wvv2) {
    int idx = blockIdx.x * blockDim.x + threadIdx.x;
    if (idx >= N_ALL) return;
    const float c0  = rsqrtf(5120.f);
    const float cvv = c0 * rsqrtf(3.f);
    const float c1  = rsqrtf(2048.f);
    const float c2  = 0.03125f;
    const float is2 = 0.70710678118654752f;
    const float is6 = 0.40824829046386302f;

    if (idx < N_CAT) {
        int k = idx >> 6, p = idx & 63;
        float val = 0.f;
        if (k < 2080) {
            int u, v; pair_decode(k, 64, u, v);
            val = c0 * Wss0[(u * 64 + v) * 64 + p];
            if (u != v) val += c0 * Wss0[(v * 64 + u) * 64 + p];
        } else if (k < 2608) {
            int u, v; pair_decode(k - 2080, 32, u, v);
            val = cvv * Wvv0[(u * 32 + v) * 64 + p];
            if (u != v) val += cvv * Wvv0[(v * 32 + u) * 64 + p];
        }
        d_Wcat[idx] = __float2half_rn(val);
    } else if (idx < B_C2) {
        int o = idx - B_C1;
        int u = o >> 10, n = o & 1023;
        int q = n >> 5, v = n & 31;
        d_Wc1[o] = __float2half_rn(c1 * Wsv1[u * 1024 + v * 32 + q]);
    } else if (idx < B_PR) {
        int o = idx - B_C2;
        int k2 = o >> 4, r = o & 15;
        int pg = k2 / 80, rem = k2 % 80;
        int m = rem >> 4, pi = rem & 15;
        int pair = pg * 16 + pi;
        int u, v; pair_decode(pair, 32, u, v);
        float w = Wvv2[(u * 32 + v) * 16 + r];
        if (u != v) w += Wvv2[(v * 32 + u) * 16 + r];
        float sc = (m == 2) ? is6 : is2;
        d_Wc2[o] = __float2half_rn(c2 * sc * w);
    } else if (idx < B_PR2) {
        int k = idx - B_PR;
        unsigned short pr = 0xFFFF;
        if (k < 2080)      { int u, v; pair_decode(k, 64, u, v);        pr = (unsigned short)((u << 8) | v); }
        else if (k < 2608) { int u, v; pair_decode(k - 2080, 32, u, v); pr = (unsigned short)((u << 8) | v); }
        d_pairs[k] = pr;
    } else if (idx < B_G) {
        int k = idx - B_PR2;
        int u, v; pair_decode(k, 32, u, v);
        d_pairs2[k] = (unsigned short)((u << 8) | v);
    } else {
        int i = idx - B_G;
        d_g[i] = tanhf(gates[i]);
    }
}

// ================= main kernel =================
__global__ __launch_bounds__(THREADS, 2) void nltsq_main(
    const float* __restrict__ feats, float* __restrict__ out) {
    extern __shared__ char smem[];
    __half* sT = (__half*)(smem + OFF_ST);
    __half* vT = (__half*)(smem + OFF_VT);

    const int tid  = threadIdx.x;
    const int wid  = tid >> 5;
    const int lane = tid & 31;
    const int wrow = wid * 16;
    const int nodeBase = blockIdx.x * CTA_M;

    // ---- Phase A: load + activate (vectorized gmem reads, transposed fp16 stores) ----
    for (int idx = tid; idx < CTA_M * 40; idx += THREADS) {
        int n = idx / 40, c4 = idx % 40;
        float4 f = ((const float4*)(feats + (size_t)(nodeBase + n) * 160))[c4];
        int c = c4 * 4;
        if (c < 64) {
            sT[(c + 0) * LD + n] = __float2half_rn(tanhf(f.x));
            sT[(c + 1) * LD + n] = __float2half_rn(tanhf(f.y));
            sT[(c + 2) * LD + n] = __float2half_rn(tanhf(f.z));
            sT[(c + 3) * LD + n] = __float2half_rn(tanhf(f.w));
        } else {
            int j = c - 64;
            vT[(j + 0) * LD + n] = __float2half_rn(f.x * d_g[(j + 0) / 3]);
            vT[(j + 1) * LD + n] = __float2half_rn(f.y * d_g[(j + 1) / 3]);
            vT[(j + 2) * LD + n] = __float2half_rn(f.z * d_g[(j + 2) / 3]);
            vT[(j + 3) * LD + n] = __float2half_rn(f.w * d_g[(j + 3) / 3]);
        }
    }

    const int k4  = tid >> 2;   // 0..63 (WB store mapping)
    const int qtr = tid & 3;
    const int kr2 = tid >> 3;   // 0..31 (build: rows 2*kr2, 2*kr2+1 -- consecutive, share u)
    const int m8  = tid & 7;    //        m-oct (16B granularity, conflict-free)

    float4 w0, w1;
    {   // prefetch Wcat chunk 0
        const float4* src = (const float4*)(d_Wcat + (size_t)k4 * 64 + qtr * 16);
        w0 = src[0]; w1 = src[1];
    }
    __syncthreads();

    // ======== GEMM 0: out0[128x64] = X[128x2624] @ Wcat (single-sync pipeline) ========
    {
        // warp tile: (M32, N32). wm = wid>>1 (0..3), wn = wid&1 (0..1)
        const int mrow = (wid >> 1) * 32;
        const int ncol = (wid & 1) * 32;
        wmma::fragment<wmma::accumulator, 16, 16, 16, float> acc[2][2];
        #pragma unroll
        for (int i = 0; i < 2; i++)
            #pragma unroll
            for (int j = 0; j < 2; j++) wmma::fill_fragment(acc[i][j], 0.f);

        for (int kc = 0; kc < KCH0; kc++) {
            __half* XT = (__half*)(smem + ((kc & 1) ? C_XT1 : C_XT0));
            __half* WB = (__half*)(smem + ((kc & 1) ? C_WB1 : C_WB0));
            {   // store prefetched W chunk
                float4* dst = (float4*)(WB + k4 * WB_LD + qtr * 16);
                dst[0] = w0; dst[1] = w1;
            }
            // build X rows 2*kr2 and 2*kr2+1 (consecutive pairs share u -> reuse loads)
            {
                int kbase = kc * 64 + 2 * kr2;
                unsigned int pr1 = d_pairs[kbase];
                unsigned int pr2 = d_pairs[kbase + 1];
                int u1 = pr1 >> 8, v1 = pr1 & 255;
                int u2 = pr2 >> 8, v2 = pr2 & 255;
                __half* xb1 = XT + (2 * kr2) * LD + m8 * 8;
                __half* xb2 = xb1 + LD;
                if (kbase < 2080) {           // both rows ss (boundary 2080 is even)
                    const __half* su = sT + u1 * LD + m8 * 8;
                    H8 a0 = *(const H8*)(su), a1h = *(const H8*)(su + 64);
                    {
                        const __half* sv = sT + v1 * LD + m8 * 8;
                        H8 b0 = *(const H8*)(sv), b1h = *(const H8*)(sv + 64), r0, r1;
                        #pragma unroll
                        for (int j = 0; j < 4; j++) {
                            r0.h[j] = __hmul2(a0.h[j], b0.h[j]);
                            r1.h[j] = __hmul2(a1h.h[j], b1h.h[j]);
                        }
                        *(H8*)(xb1) = r0; *(H8*)(xb1 + 64) = r1;
                    }
                    if (u2 != u1) {
                        const __half* su2 = sT + u2 * LD + m8 * 8;
                        a0 = *(const H8*)(su2); a1h = *(const H8*)(su2 + 64);
                    }
                    {
                        const __half* sv = sT + v2 * LD + m8 * 8;
                        H8 b0 = *(const H8*)(sv), b1h = *(const H8*)(sv + 64), r0, r1;
                        #pragma unroll
                        for (int j = 0; j < 4; j++) {
                            r0.h[j] = __hmul2(a0.h[j], b0.h[j]);
                            r1.h[j] = __hmul2(a1h.h[j], b1h.h[j]);
                        }
                        *(H8*)(xb2) = r0; *(H8*)(xb2 + 64) = r1;
                    }
                } else if (kbase < 2608) {    // both rows vv (boundary 2608 is even)
                    const __half* au = vT + u1 * 3 * LD + m8 * 8;
                    H8 x00 = *(const H8*)(au),          x01 = *(const H8*)(au + 64);
                    H8 x10 = *(const H8*)(au + LD),     x11 = *(const H8*)(au + LD + 64);
                    H8 x20 = *(const H8*)(au + 2 * LD), x21 = *(const H8*)(au + 2 * LD + 64);
                    {
                        const __half* bv = vT + v1 * 3 * LD + m8 * 8;
                        H8 y00 = *(const H8*)(bv),          y01 = *(const H8*)(bv + 64);
                        H8 y10 = *(const H8*)(bv + LD),     y11 = *(const H8*)(bv + LD + 64);
                        H8 y20 = *(const H8*)(bv + 2 * LD), y21 = *(const H8*)(bv + 2 * LD + 64);
                        H8 r0, r1;
                        #pragma unroll
                        for (int j = 0; j < 4; j++) {
                            r0.h[j] = __hfma2(x00.h[j], y00.h[j],
                                      __hfma2(x10.h[j], y10.h[j], __hmul2(x20.h[j], y20.h[j])));
                            r1.h[j] = __hfma2(x01.h[j], y01.h[j],
                                      __hfma2(x11.h[j], y11.h[j], __hmul2(x21.h[j], y21.h[j])));
                        }
                        *(H8*)(xb1) = r0; *(H8*)(xb1 + 64) = r1;
                    }
                    if (u2 != u1) {
                        const __half* au2 = vT + u2 * 3 * LD + m8 * 8;
                        x00 = *(const H8*)(au2);          x01 = *(const H8*)(au2 + 64);
                        x10 = *(const H8*)(au2 + LD);     x11 = *(const H8*)(au2 + LD + 64);
                        x20 = *(const H8*)(au2 + 2 * LD); x21 = *(const H8*)(au2 + 2 * LD + 64);
                    }
                    {
                        const __half* bv = vT + v2 * 3 * LD + m8 * 8;
                        H8 y00 = *(const H8*)(bv),          y01 = *(const H8*)(bv + 64);
                        H8 y10 = *(const H8*)(bv + LD),     y11 = *(const H8*)(bv + LD + 64);
                        H8 y20 = *(const H8*)(bv + 2 * LD), y21 = *(const H8*)(bv + 2 * LD + 64);
                        H8 r0, r1;
                        #pragma unroll
                        for (int j = 0; j < 4; j++) {
                            r0.h[j] = __hfma2(x00.h[j], y00.h[j],
                                      __hfma2(x10.h[j], y10.h[j], __hmul2(x20.h[j], y20.h[j])));
                            r1.h[j] = __hfma2(x01.h[j], y01.h[j],
                                      __hfma2(x11.h[j], y11.h[j], __hmul2(x21.h[j], y21.h[j])));
                        }
                        *(H8*)(xb2) = r0; *(H8*)(xb2 + 64) = r1;
                    }
                } else {                      // both rows pad
                    H8 z;
                    #pragma unroll
                    for (int j = 0; j < 4; j++) z.h[j] = __half2half2(__half(0.f));
                    *(H8*)(xb1) = z; *(H8*)(xb1 + 64) = z;
                    *(H8*)(xb2) = z; *(H8*)(xb2 + 64) = z;
                }
            }
            if (kc + 1 < KCH0) {   // prefetch next W chunk
                const float4* src = (const float4*)(d_Wcat + (size_t)(kc + 1) * 64 * 64
                                                    + (size_t)k4 * 64 + qtr * 16);
                w0 = src[0]; w1 = src[1];
            }
            __syncthreads();        // tiles ready -> mma; WAR covered by next iter's sync
            #pragma unroll
            for (int ks = 0; ks < 4; ks++) {
                wmma::fragment<wmma::matrix_a, 16, 16, 16, __half, wmma::col_major> a[2];
                wmma::fragment<wmma::matrix_b, 16, 16, 16, __half, wmma::row_major> b[2];
                #pragma unroll
                for (int i = 0; i < 2; i++)
                    wmma::load_matrix_sync(a[i], XT + ks * 16 * LD + mrow + i * 16, LD);
                #pragma unroll
                for (int j = 0; j < 2; j++)
                    wmma::load_matrix_sync(b[j], WB + ks * 16 * WB_LD + ncol + j * 16, WB_LD);
                #pragma unroll
                for (int i = 0; i < 2; i++)
                    #pragma unroll
                    for (int j = 0; j < 2; j++)
                        wmma::mma_sync(acc[i][j], a[i], b[j], acc[i][j]);
            }
        }
        #pragma unroll
        for (int i = 0; i < 2; i++)
            #pragma unroll
            for (int j = 0; j < 2; j++)
                wmma::store_matrix_sync(out + (size_t)(nodeBase + mrow + i * 16) * DOUT
                                        + ncol + j * 16, acc[i][j], DOUT, wmma::mem_row_major);
    }

    // ---- cache own-strip node's v-column (node en) as 48 half2 ----
    const int en   = wrow + (lane & 15);    // node within OWN warp's strip
    const int qsel = lane >> 4;
    uint32_t vc[48];
    #pragma unroll
    for (int r = 0; r < 48; r++) {
        __half lo = vT[(2 * r) * LD + en];
        __half hi = vT[(2 * r + 1) * LD + en];
        vc[r] = (uint32_t)__half_as_ushort(lo) | ((uint32_t)__half_as_ushort(hi) << 16);
    }
    float* orow = out + (size_t)(nodeBase + en) * DOUT;

    __syncthreads();   // GEMM0 mma fully done before region C reuse (YS overlays XT/WB)

    // ======== GEMM 1: Y = sH @ Wc1 — warp-independent, NO CTA syncs ========
    // B fragments stream directly from gmem (L1-cached, shared 8x in-CTA).
    // YS staging + epilogue are own-strip -> __syncwarp only.
    {
        wmma::fragment<wmma::matrix_a, 16, 16, 16, __half, wmma::col_major> a1[4];
        #pragma unroll
        for (int ks = 0; ks < 4; ks++)
            wmma::load_matrix_sync(a1[ks], sT + ks * 16 * LD + wrow, LD);
        float* YS = (float*)(smem + C1_YS);     // row-major [128][Y1_LD]

        for (int nc = 0; nc < 16; nc++) {
            #pragma unroll
            for (int nt = 0; nt < 4; nt++) {
                wmma::fragment<wmma::accumulator, 16, 16, 16, float> acc;
                wmma::fill_fragment(acc, 0.f);
                #pragma unroll
                for (int ks = 0; ks < 4; ks++) {
                    wmma::fragment<wmma::matrix_b, 16, 16, 16, __half, wmma::row_major> b;
                    wmma::load_matrix_sync(b, d_Wc1 + (size_t)(ks * 16) * 1024
                                           + nc * 64 + nt * 16, 1024);
                    wmma::mma_sync(acc, a1[ks], b, acc);
                }
                wmma::store_matrix_sync(YS + wrow * Y1_LD + nt * 16, acc, Y1_LD,
                                        wmma::mem_row_major);
            }
            __syncwarp();   // own-strip YS visible to own warp
            {   // epilogue: node en (own strip), q = nc*2 + qsel, vectorized reads
                float a0 = 0.f, a1s = 0.f, a2 = 0.f;
                const float4* yv4 = (const float4*)(YS + en * Y1_LD + qsel * 32);
                #pragma unroll
                for (int bq = 0; bq < 4; bq++) {
                    float4 ya = yv4[2 * bq], yb = yv4[2 * bq + 1];
                    float yy[8] = {ya.x, ya.y, ya.z, ya.w, yb.x, yb.y, yb.z, yb.w};
                    #pragma unroll
                    for (int t = 0; t < 4; t++) {
                        int v2 = bq * 4 + t;
                        __half2 p0 = *(__half2*)&vc[3 * v2];
                        __half2 p1 = *(__half2*)&vc[3 * v2 + 1];
                        __half2 p2 = *(__half2*)&vc[3 * v2 + 2];
                        float y0 = yy[2 * t], y1 = yy[2 * t + 1];
                        a0  += y0 * __low2float(p0);  a1s += y0 * __high2float(p0); a2 += y0 * __low2float(p1);
                        a0  += y1 * __high2float(p1); a1s += y1 * __low2float(p2);  a2 += y1 * __high2float(p2);
                    }
                }
                int q = nc * 2 + qsel;
                orow[64 + q * 3]     = a0;
                orow[64 + q * 3 + 1] = a1s;
                orow[64 + q * 3 + 2] = a2;
            }
            __syncwarp();   // epilogue reads done before next chunk's YS stores
        }
    }
    __syncthreads();   // GEMM1 done before region C reuse

    // ======== GEMM 2: out2 via symmetric pair features (B direct from gmem) ========
    {
        wmma::fragment<wmma::accumulator, 16, 16, 16, float> acc2[5];
        #pragma unroll
        for (int m = 0; m < 5; m++) wmma::fill_fragment(acc2[m], 0.f);

        const int pi = tid >> 4;      // pair in group (0..15)
        const int mh = tid & 15;      // m-chunk of 8 nodes

        for (int pg = 0; pg < PGRPS; pg++) {
            __half* XT = (__half*)(smem + ((pg & 1) ? C2_XT1 : C2_XT0));
            unsigned int pr = d_pairs2[pg * 16 + pi];
            int u = pr >> 8, v = pr & 255;
            H8 ua0 = *(const H8*)(vT + (u * 3 + 0) * LD + mh * 8);
            H8 ua1 = *(const H8*)(vT + (u * 3 + 1) * LD + mh * 8);
            H8 ua2 = *(const H8*)(vT + (u * 3 + 2) * LD + mh * 8);
            H8 vb0 = *(const H8*)(vT + (v * 3 + 0) * LD + mh * 8);
            H8 vb1 = *(const H8*)(vT + (v * 3 + 1) * LD + mh * 8);
            H8 vb2 = *(const H8*)(vT + (v * 3 + 2) * LD + mh * 8);
            H8 r0, r1, r2, r3, r4;
            #pragma unroll
            for (int j = 0; j < 4; j++) {
                __half2 a0 = ua0.h[j], a1 = ua1.h[j], a2 = ua2.h[j];
                __half2 b0 = vb0.h[j], b1 = vb1.h[j], b2 = vb2.h[j];
                __half2 aa = __hmul2(a0, b0);
                __half2 bb = __hmul2(a1, b1);
                __half2 cc = __hmul2(a2, b2);
                r0.h[j] = __hfma2(a0, b1, __hmul2(a1, b0));
                r1.h[j] = __hfma2(a1, b2, __hmul2(a2, b1));
                r2.h[j] = __hsub2(__hsub2(__hadd2(cc, cc), aa), bb);
                r3.h[j] = __hfma2(a0, b2, __hmul2(a2, b0));
                r4.h[j] = __hsub2(aa, bb);
            }
            *(H8*)(XT + (0 * 16 + pi) * LD + mh * 8) = r0;
            *(H8*)(XT + (1 * 16 + pi) * LD + mh * 8) = r1;
            *(H8*)(XT + (2 * 16 + pi) * LD + mh * 8) = r2;
            *(H8*)(XT + (3 * 16 + pi) * LD + mh * 8) = r3;
            *(H8*)(XT + (4 * 16 + pi) * LD + mh * 8) = r4;
            __syncthreads();
            #pragma unroll
            for (int mf = 0; mf < 5; mf++) {
                wmma::fragment<wmma::matrix_a, 16, 16, 16, __half, wmma::col_major> a;
                wmma::fragment<wmma::matrix_b, 16, 16, 16, __half, wmma::row_major> b;
                wmma::load_matrix_sync(a, XT + (mf * 16) * LD + wrow, LD);
                wmma::load_matrix_sync(b, d_Wc2 + (size_t)(pg * 80 + mf * 16) * 16, 16);
                wmma::mma_sync(acc2[mf], a, b, acc2[mf]);
            }
        }
        __syncthreads();   // all mma done before staging overwrites region C
        float* YS = (float*)(smem + C2_YS);
        #pragma unroll
        for (int m = 0; m < 5; m++)
            wmma::store_matrix_sync(YS + wrow + (m * 16) * YS_LD, acc2[m], YS_LD,
                                    wmma::mem_col_major);
        __syncthreads();
        for (int idx = tid; idx < CTA_M * 80; idx += THREADS) {
            int n = idx / 80, c = idx % 80;
            int m = c >> 4, r = c & 15;
            out[(size_t)(nodeBase + n) * DOUT + 160 + r * 5 + m] = YS[n + c * YS_LD];
        }
    }
}

// ================= launch =================
extern "C" void kernel_launch(void* const* d_in, const int* in_sizes, int n_in,
                              void* d_out, int out_size) {
    const float* feats = (const float*)d_in[0];
    const float* gates = (const float*)d_in[1];
    const float* Wss0  = (const float*)d_in[2];
    const float* Wsv1  = (const float*)d_in[3];
    const float* Wvv0  = (const float*)d_in[4];
    const float* Wvv2  = (const float*)d_in[5];
    float* out = (float*)d_out;

    static bool attr_set = false;
    if (!attr_set) {
        cudaFuncSetAttribute(nltsq_main, cudaFuncAttributeMaxDynamicSharedMemorySize, SMEM_TOTAL);
        attr_set = true;
    }

    prep_all<<<(N_ALL + 255) / 256, 256>>>(gates, Wss0, Wsv1, Wvv0, Wvv2);
    nltsq_main<<<NODES / CTA_M, THREADS, SMEM_TOTAL>>>(feats, out);
}

// round 15
// speedup vs baseline: 1.5193x; 1.5193x over previous
#include <cuda_runtime.h>
#include <cuda_fp16.h>
#include <mma.h>
#include <math.h>
#include <stdint.h>

using namespace nvcuda;

// ================= problem constants =================
#define NODES   32768
#define CTA_M   128
#define THREADS 256
#define DOUT    240
#define KTOT    2624            // 2080 ss + 528 vv + 16 pad = 41*64
#define KCH0    41
#define NPAIR2  528
#define PGRPS   33              // 528/16

// ================= smem layout =================
#define LD       136            // halves
#define WB_LD    72             // halves
#define W2_LD    24             // halves
#define YS_LD    132            // floats (GEMM2 col-major staging)
#define Y1_LD    68             // floats (GEMM1 row-major staging)

#define OFF_ST   0              // sT[64][136]  half  17408
#define OFF_VT   17408          // vT[96][136]  half  26112
#define OFF_C    43520          // union region       53248
#define SMEM_TOTAL 96768

// region C sub-layouts (phase-exclusive)
#define C_XT0   (OFF_C)             // GEMM0 X tile buf0   17408
#define C_XT1   (OFF_C + 17408)     //              buf1   17408
#define C_WB0   (OFF_C + 34816)     // GEMM0 W tile buf0    9216
#define C_WB1   (OFF_C + 44032)     //              buf1    9216
#define C1_WB0  (OFF_C)             // GEMM1 W buf0         9216
#define C1_WB1  (OFF_C + 9216)      //         buf1         9216
#define C1_YS   (OFF_C + 18432)     // GEMM1 staging (row-major 128x68 f) 34816
#define C2_XT0  (OFF_C)             // GEMM2 feat buf0     21760
#define C2_XT1  (OFF_C + 21760)     //            buf1     21760
#define C2_WB0  (OFF_C + 43520)     // GEMM2 W buf0         3840
#define C2_WB1  (OFF_C + 47360)     //          buf1        3840
#define C2_YS   (OFF_C)             // GEMM2 staging (post-loop) 42240

struct alignas(16) H8 { __half2 h[4]; };

// ---- cp.async helpers ----
__device__ __forceinline__ uint32_t s2u(const void* p) {
    return (uint32_t)__cvta_generic_to_shared(p);
}
__device__ __forceinline__ void cp16(uint32_t dst, const void* src) {
    asm volatile("cp.async.ca.shared.global [%0], [%1], 16;" :: "r"(dst), "l"(src));
}
#define CP_COMMIT() asm volatile("cp.async.commit_group;" ::: "memory")
#define CP_WAIT0()  asm volatile("cp.async.wait_group 0;" ::: "memory")

// ================= preprocessed weights (gmem) =================
__device__ __half d_Wcat[KTOT * 64];        // [k][p]
__device__ __half d_Wc1 [64 * 1024];        // [u][q*32+v]
__device__ __half d_Wc2 [PGRPS * 80 * 16];  // [(pg*80 + m*16 + pi)][r]
__device__ unsigned short d_pairs [KTOT];
__device__ unsigned short d_pairs2[NPAIR2];
__device__ float d_g[32];

#define N_CAT (KTOT * 64)
#define B_C1  N_CAT
#define N_C1  (64 * 1024)
#define B_C2  (B_C1 + N_C1)
#define N_C2  (PGRPS * 80 * 16)
#define B_PR  (B_C2 + N_C2)
#define B_PR2 (B_PR + KTOT)
#define B_G   (B_PR2 + NPAIR2)
#define N_ALL (B_G + 32)

// ================= prep kernel =================
__device__ __forceinline__ void pair_decode(int k, int width, int& u, int& v) {
    int uu = 0, rem = k;
    while (rem >= width - uu) { rem -= width - uu; uu++; }
    u = uu; v = uu + rem;
}

__global__ void prep_all(const float* __restrict__ gates, const float* __restrict__ Wss0,
                         const float* __restrict__ Wsv1, const float* __restrict__ Wvv0,
                         const float* __restrict__ Wvv2) {
    int idx = blockIdx.x * blockDim.x + threadIdx.x;
    if (idx >= N_ALL) return;
    const float c0  = rsqrtf(5120.f);
    const float cvv = c0 * rsqrtf(3.f);
    const float c1  = rsqrtf(2048.f);
    const float c2  = 0.03125f;
    const float is2 = 0.70710678118654752f;
    const float is6 = 0.40824829046386302f;

    if (idx < N_CAT) {
        int k = idx >> 6, p = idx & 63;
        float val = 0.f;
        if (k < 2080) {
            int u, v; pair_decode(k, 64, u, v);
            val = c0 * Wss0[(u * 64 + v) * 64 + p];
            if (u != v) val += c0 * Wss0[(v * 64 + u) * 64 + p];
        } else if (k < 2608) {
            int u, v; pair_decode(k - 2080, 32, u, v);
            val = cvv * Wvv0[(u * 32 + v) * 64 + p];
            if (u != v) val += cvv * Wvv0[(v * 32 + u) * 64 + p];
        }
        d_Wcat[idx] = __float2half_rn(val);
    } else if (idx < B_C2) {
        int o = idx - B_C1;
        int u = o >> 10, n = o & 1023;
        int q = n >> 5, v = n & 31;
        d_Wc1[o] = __float2half_rn(c1 * Wsv1[u * 1024 + v * 32 + q]);
    } else if (idx < B_PR) {
        int o = idx - B_C2;
        int k2 = o >> 4, r = o & 15;
        int pg = k2 / 80, rem = k2 % 80;
        int m = rem >> 4, pi = rem & 15;
        int pair = pg * 16 + pi;
        int u, v; pair_decode(pair, 32, u, v);
        float w = Wvv2[(u * 32 + v) * 16 + r];
        if (u != v) w += Wvv2[(v * 32 + u) * 16 + r];
        float sc = (m == 2) ? is6 : is2;
        d_Wc2[o] = __float2half_rn(c2 * sc * w);
    } else if (idx < B_PR2) {
        int k = idx - B_PR;
        unsigned short pr = 0xFFFF;
        if (k < 2080)      { int u, v; pair_decode(k, 64, u, v);        pr = (unsigned short)((u << 8) | v); }
        else if (k < 2608) { int u, v; pair_decode(k - 2080, 32, u, v); pr = (unsigned short)((u << 8) | v); }
        d_pairs[k] = pr;
    } else if (idx < B_G) {
        int k = idx - B_PR2;
        int u, v; pair_decode(k, 32, u, v);
        d_pairs2[k] = (unsigned short)((u << 8) | v);
    } else {
        int i = idx - B_G;
        d_g[i] = tanhf(gates[i]);
    }
}

// ================= main kernel =================
__global__ __launch_bounds__(THREADS, 2) void nltsq_main(
    const float* __restrict__ feats, float* __restrict__ out) {
    extern __shared__ char smem[];
    __half* sT = (__half*)(smem + OFF_ST);
    __half* vT = (__half*)(smem + OFF_VT);

    const int tid  = threadIdx.x;
    const int wid  = tid >> 5;
    const int lane = tid & 31;
    const int wrow = wid * 16;
    const int nodeBase = blockIdx.x * CTA_M;

    // ---- Phase A: load + activate (vectorized gmem reads, transposed fp16 stores) ----
    for (int idx = tid; idx < CTA_M * 40; idx += THREADS) {
        int n = idx / 40, c4 = idx % 40;
        float4 f = ((const float4*)(feats + (size_t)(nodeBase + n) * 160))[c4];
        int c = c4 * 4;
        if (c < 64) {
            sT[(c + 0) * LD + n] = __float2half_rn(tanhf(f.x));
            sT[(c + 1) * LD + n] = __float2half_rn(tanhf(f.y));
            sT[(c + 2) * LD + n] = __float2half_rn(tanhf(f.z));
            sT[(c + 3) * LD + n] = __float2half_rn(tanhf(f.w));
        } else {
            int j = c - 64;
            vT[(j + 0) * LD + n] = __float2half_rn(f.x * d_g[(j + 0) / 3]);
            vT[(j + 1) * LD + n] = __float2half_rn(f.y * d_g[(j + 1) / 3]);
            vT[(j + 2) * LD + n] = __float2half_rn(f.z * d_g[(j + 2) / 3]);
            vT[(j + 3) * LD + n] = __float2half_rn(f.w * d_g[(j + 3) / 3]);
        }
    }

    const int k4  = tid >> 2;   // 0..63 (WB staging mapping)
    const int qtr = tid & 3;
    const int kr2 = tid >> 3;   // 0..31 (build: rows 2*kr2, 2*kr2+1 -- consecutive, share u)
    const int m8  = tid & 7;    //        m-oct (16B granularity, conflict-free)

    // this thread's W-staging slot (32B) in each buffer
    const uint32_t wb0 = s2u(smem + C_WB0) + (k4 * WB_LD + qtr * 16) * 2;
    const uint32_t wb1 = s2u(smem + C_WB1) + (k4 * WB_LD + qtr * 16) * 2;
    const __half*  wsrc0 = d_Wcat + (size_t)k4 * 64 + qtr * 16;

    // prologue: stage Wcat chunk 0 into WB0 via cp.async
    cp16(wb0, wsrc0);
    cp16(wb0 + 16, wsrc0 + 8);
    CP_COMMIT();
    __syncthreads();

    // ======== GEMM 0: out0[128x64] = X[128x2624] @ Wcat (single-sync pipeline) ========
    {
        // warp tile: (M32, N32). wm = wid>>1 (0..3), wn = wid&1 (0..1)
        const int mrow = (wid >> 1) * 32;
        const int ncol = (wid & 1) * 32;
        wmma::fragment<wmma::accumulator, 16, 16, 16, float> acc[2][2];
        #pragma unroll
        for (int i = 0; i < 2; i++)
            #pragma unroll
            for (int j = 0; j < 2; j++) wmma::fill_fragment(acc[i][j], 0.f);

        for (int kc = 0; kc < KCH0; kc++) {
            __half* XT = (__half*)(smem + ((kc & 1) ? C_XT1 : C_XT0));
            __half* WB = (__half*)(smem + ((kc & 1) ? C_WB1 : C_WB0));
            // build X rows 2*kr2 and 2*kr2+1 (consecutive pairs share u -> reuse loads)
            {
                int kbase = kc * 64 + 2 * kr2;
                unsigned int pr1 = d_pairs[kbase];
                unsigned int pr2 = d_pairs[kbase + 1];
                int u1 = pr1 >> 8, v1 = pr1 & 255;
                int u2 = pr2 >> 8, v2 = pr2 & 255;
                __half* xb1 = XT + (2 * kr2) * LD + m8 * 8;
                __half* xb2 = xb1 + LD;
                if (kbase < 2080) {           // both rows ss (boundary 2080 is even)
                    const __half* su = sT + u1 * LD + m8 * 8;
                    H8 a0 = *(const H8*)(su), a1h = *(const H8*)(su + 64);
                    {
                        const __half* sv = sT + v1 * LD + m8 * 8;
                        H8 b0 = *(const H8*)(sv), b1h = *(const H8*)(sv + 64), r0, r1;
                        #pragma unroll
                        for (int j = 0; j < 4; j++) {
                            r0.h[j] = __hmul2(a0.h[j], b0.h[j]);
                            r1.h[j] = __hmul2(a1h.h[j], b1h.h[j]);
                        }
                        *(H8*)(xb1) = r0; *(H8*)(xb1 + 64) = r1;
                    }
                    if (u2 != u1) {
                        const __half* su2 = sT + u2 * LD + m8 * 8;
                        a0 = *(const H8*)(su2); a1h = *(const H8*)(su2 + 64);
                    }
                    {
                        const __half* sv = sT + v2 * LD + m8 * 8;
                        H8 b0 = *(const H8*)(sv), b1h = *(const H8*)(sv + 64), r0, r1;
                        #pragma unroll
                        for (int j = 0; j < 4; j++) {
                            r0.h[j] = __hmul2(a0.h[j], b0.h[j]);
                            r1.h[j] = __hmul2(a1h.h[j], b1h.h[j]);
                        }
                        *(H8*)(xb2) = r0; *(H8*)(xb2 + 64) = r1;
                    }
                } else if (kbase < 2608) {    // both rows vv (boundary 2608 is even)
                    const __half* au = vT + u1 * 3 * LD + m8 * 8;
                    H8 x00 = *(const H8*)(au),          x01 = *(const H8*)(au + 64);
                    H8 x10 = *(const H8*)(au + LD),     x11 = *(const H8*)(au + LD + 64);
                    H8 x20 = *(const H8*)(au + 2 * LD), x21 = *(const H8*)(au + 2 * LD + 64);
                    {
                        const __half* bv = vT + v1 * 3 * LD + m8 * 8;
                        H8 y00 = *(const H8*)(bv),          y01 = *(const H8*)(bv + 64);
                        H8 y10 = *(const H8*)(bv + LD),     y11 = *(const H8*)(bv + LD + 64);
                        H8 y20 = *(const H8*)(bv + 2 * LD), y21 = *(const H8*)(bv + 2 * LD + 64);
                        H8 r0, r1;
                        #pragma unroll
                        for (int j = 0; j < 4; j++) {
                            r0.h[j] = __hfma2(x00.h[j], y00.h[j],
                                      __hfma2(x10.h[j], y10.h[j], __hmul2(x20.h[j], y20.h[j])));
                            r1.h[j] = __hfma2(x01.h[j], y01.h[j],
                                      __hfma2(x11.h[j], y11.h[j], __hmul2(x21.h[j], y21.h[j])));
                        }
                        *(H8*)(xb1) = r0; *(H8*)(xb1 + 64) = r1;
                    }
                    if (u2 != u1) {
                        const __half* au2 = vT + u2 * 3 * LD + m8 * 8;
                        x00 = *(const H8*)(au2);          x01 = *(const H8*)(au2 + 64);
                        x10 = *(const H8*)(au2 + LD);     x11 = *(const H8*)(au2 + LD + 64);
                        x20 = *(const H8*)(au2 + 2 * LD); x21 = *(const H8*)(au2 + 2 * LD + 64);
                    }
                    {
                        const __half* bv = vT + v2 * 3 * LD + m8 * 8;
                        H8 y00 = *(const H8*)(bv),          y01 = *(const H8*)(bv + 64);
                        H8 y10 = *(const H8*)(bv + LD),     y11 = *(const H8*)(bv + LD + 64);
                        H8 y20 = *(const H8*)(bv + 2 * LD), y21 = *(const H8*)(bv + 2 * LD + 64);
                        H8 r0, r1;
                        #pragma unroll
                        for (int j = 0; j < 4; j++) {
                            r0.h[j] = __hfma2(x00.h[j], y00.h[j],
                                      __hfma2(x10.h[j], y10.h[j], __hmul2(x20.h[j], y20.h[j])));
                            r1.h[j] = __hfma2(x01.h[j], y01.h[j],
                                      __hfma2(x11.h[j], y11.h[j], __hmul2(x21.h[j], y21.h[j])));
                        }
                        *(H8*)(xb2) = r0; *(H8*)(xb2 + 64) = r1;
                    }
                } else {                      // both rows pad
                    H8 z;
                    #pragma unroll
                    for (int j = 0; j < 4; j++) z.h[j] = __half2half2(__half(0.f));
                    *(H8*)(xb1) = z; *(H8*)(xb1 + 64) = z;
                    *(H8*)(xb2) = z; *(H8*)(xb2 + 64) = z;
                }
            }
            CP_WAIT0();             // this thread's pending W copy (chunk kc) done
            __syncthreads();        // tiles visible to all; all warps past mma(kc-1)
            if (kc + 1 < KCH0) {    // WAR-safe post-sync: stage chunk kc+1 into other buf
                const __half* src = d_Wcat + (size_t)(kc + 1) * 64 * 64
                                    + (size_t)k4 * 64 + qtr * 16;
                uint32_t dst = (kc & 1) ? wb0 : wb1;
                cp16(dst, src);
                cp16(dst + 16, src + 8);
                CP_COMMIT();
            }
            #pragma unroll
            for (int ks = 0; ks < 4; ks++) {
                wmma::fragment<wmma::matrix_a, 16, 16, 16, __half, wmma::col_major> a[2];
                wmma::fragment<wmma::matrix_b, 16, 16, 16, __half, wmma::row_major> b[2];
                #pragma unroll
                for (int i = 0; i < 2; i++)
                    wmma::load_matrix_sync(a[i], XT + ks * 16 * LD + mrow + i * 16, LD);
                #pragma unroll
                for (int j = 0; j < 2; j++)
                    wmma::load_matrix_sync(b[j], WB + ks * 16 * WB_LD + ncol + j * 16, WB_LD);
                #pragma unroll
                for (int i = 0; i < 2; i++)
                    #pragma unroll
                    for (int j = 0; j < 2; j++)
                        wmma::mma_sync(acc[i][j], a[i], b[j], acc[i][j]);
            }
        }
        #pragma unroll
        for (int i = 0; i < 2; i++)
            #pragma unroll
            for (int j = 0; j < 2; j++)
                wmma::store_matrix_sync(out + (size_t)(nodeBase + mrow + i * 16) * DOUT
                                        + ncol + j * 16, acc[i][j], DOUT, wmma::mem_row_major);
    }

    // ---- cache own-strip node's v-column (node en) as 48 half2 ----
    const int en   = wrow + (lane & 15);    // node within OWN warp's strip
    const int qsel = lane >> 4;
    uint32_t vc[48];
    #pragma unroll
    for (int r = 0; r < 48; r++) {
        __half lo = vT[(2 * r) * LD + en];
        __half hi = vT[(2 * r + 1) * LD + en];
        vc[r] = (uint32_t)__half_as_ushort(lo) | ((uint32_t)__half_as_ushort(hi) << 16);
    }
    float* orow = out + (size_t)(nodeBase + en) * DOUT;

    __syncthreads();   // GEMM0 mma fully done before region C reuse

    // GEMM1 staging slots
    const uint32_t c1wb0 = s2u(smem + C1_WB0) + (k4 * WB_LD + qtr * 16) * 2;
    const uint32_t c1wb1 = s2u(smem + C1_WB1) + (k4 * WB_LD + qtr * 16) * 2;
    const __half*  c1src = d_Wc1 + (size_t)k4 * 1024 + qtr * 16;

    // prologue: stage Wc1 chunk 0 (region C free: all warps past the sync above)
    cp16(c1wb0, c1src);
    cp16(c1wb0 + 16, c1src + 8);
    CP_COMMIT();

    // ======== GEMM 1: Y = sH @ Wc1 (16 chunks of 64 cols); out1 = Y . v ========
    {
        wmma::fragment<wmma::matrix_a, 16, 16, 16, __half, wmma::col_major> a1[4];
        #pragma unroll
        for (int ks = 0; ks < 4; ks++)
            wmma::load_matrix_sync(a1[ks], sT + ks * 16 * LD + wrow, LD);
        float* YS = (float*)(smem + C1_YS);     // row-major [128][Y1_LD]

        for (int nc = 0; nc < 16; nc++) {
            __half* WB = (__half*)(smem + ((nc & 1) ? C1_WB1 : C1_WB0));
            CP_WAIT0();             // chunk nc staged
            __syncthreads();        // visible to all; all warps past mma(nc-1)
            if (nc + 1 < 16) {      // WAR-safe post-sync: stage chunk nc+1
                const __half* src = c1src + (nc + 1) * 64;
                uint32_t dst = (nc & 1) ? c1wb0 : c1wb1;
                cp16(dst, src);
                cp16(dst + 16, src + 8);
                CP_COMMIT();
            }
            #pragma unroll
            for (int nt = 0; nt < 4; nt++) {
                wmma::fragment<wmma::accumulator, 16, 16, 16, float> acc;
                wmma::fill_fragment(acc, 0.f);
                #pragma unroll
                for (int ks = 0; ks < 4; ks++) {
                    wmma::fragment<wmma::matrix_b, 16, 16, 16, __half, wmma::row_major> b;
                    wmma::load_matrix_sync(b, WB + ks * 16 * WB_LD + nt * 16, WB_LD);
                    wmma::mma_sync(acc, a1[ks], b, acc);
                }
                wmma::store_matrix_sync(YS + wrow * Y1_LD + nt * 16, acc, Y1_LD,
                                        wmma::mem_row_major);
            }
            __syncwarp();   // own-strip YS visible to own warp
            {   // epilogue: node en (own strip), q = nc*2 + qsel, vectorized reads
                float a0 = 0.f, a1s = 0.f, a2 = 0.f;
                const float4* yv4 = (const float4*)(YS + en * Y1_LD + qsel * 32);
                #pragma unroll
                for (int bq = 0; bq < 4; bq++) {
                    float4 ya = yv4[2 * bq], yb = yv4[2 * bq + 1];
                    float yy[8] = {ya.x, ya.y, ya.z, ya.w, yb.x, yb.y, yb.z, yb.w};
                    #pragma unroll
                    for (int t = 0; t < 4; t++) {
                        int v2 = bq * 4 + t;
                        __half2 p0 = *(__half2*)&vc[3 * v2];
                        __half2 p1 = *(__half2*)&vc[3 * v2 + 1];
                        __half2 p2 = *(__half2*)&vc[3 * v2 + 2];
                        float y0 = yy[2 * t], y1 = yy[2 * t + 1];
                        a0  += y0 * __low2float(p0);  a1s += y0 * __high2float(p0); a2 += y0 * __low2float(p1);
                        a0  += y1 * __high2float(p1); a1s += y1 * __low2float(p2);  a2 += y1 * __high2float(p2);
                    }
                }
                int q = nc * 2 + qsel;
                orow[64 + q * 3]     = a0;
                orow[64 + q * 3 + 1] = a1s;
                orow[64 + q * 3 + 2] = a2;
            }
            __syncwarp();   // epilogue reads done before next chunk's YS stores
        }
    }
    __syncthreads();   // GEMM1 done before region C reuse

    // ======== GEMM 2: out2 via symmetric pair features ========
    {
        wmma::fragment<wmma::accumulator, 16, 16, 16, float> acc2[5];
        #pragma unroll
        for (int m = 0; m < 5; m++) wmma::fill_fragment(acc2[m], 0.f);

        const int pi = tid >> 4;      // pair in group (0..15)
        const int mh = tid & 15;      // m-chunk of 8 nodes
        float4 w2;
        if (tid < 160) {
            const float4* src = (const float4*)(d_Wc2 + (size_t)(tid >> 1) * 16 + (tid & 1) * 8);
            w2 = src[0];
        }

        for (int pg = 0; pg < PGRPS; pg++) {
            __half* XT = (__half*)(smem + ((pg & 1) ? C2_XT1 : C2_XT0));
            __half* WB = (__half*)(smem + ((pg & 1) ? C2_WB1 : C2_WB0));
            if (tid < 160) *(float4*)(WB + (tid >> 1) * W2_LD + (tid & 1) * 8) = w2;
            unsigned int pr = d_pairs2[pg * 16 + pi];
            int u = pr >> 8, v = pr & 255;
            H8 ua0 = *(const H8*)(vT + (u * 3 + 0) * LD + mh * 8);
            H8 ua1 = *(const H8*)(vT + (u * 3 + 1) * LD + mh * 8);
            H8 ua2 = *(const H8*)(vT + (u * 3 + 2) * LD + mh * 8);
            H8 vb0 = *(const H8*)(vT + (v * 3 + 0) * LD + mh * 8);
            H8 vb1 = *(const H8*)(vT + (v * 3 + 1) * LD + mh * 8);
            H8 vb2 = *(const H8*)(vT + (v * 3 + 2) * LD + mh * 8);
            H8 r0, r1, r2, r3, r4;
            #pragma unroll
            for (int j = 0; j < 4; j++) {
                __half2 a0 = ua0.h[j], a1 = ua1.h[j], a2 = ua2.h[j];
                __half2 b0 = vb0.h[j], b1 = vb1.h[j], b2 = vb2.h[j];
                __half2 aa = __hmul2(a0, b0);
                __half2 bb = __hmul2(a1, b1);
                __half2 cc = __hmul2(a2, b2);
                r0.h[j] = __hfma2(a0, b1, __hmul2(a1, b0));
                r1.h[j] = __hfma2(a1, b2, __hmul2(a2, b1));
                r2.h[j] = __hsub2(__hsub2(__hadd2(cc, cc), aa), bb);
                r3.h[j] = __hfma2(a0, b2, __hmul2(a2, b0));
                r4.h[j] = __hsub2(aa, bb);
            }
            *(H8*)(XT + (0 * 16 + pi) * LD + mh * 8) = r0;
            *(H8*)(XT + (1 * 16 + pi) * LD + mh * 8) = r1;
            *(H8*)(XT + (2 * 16 + pi) * LD + mh * 8) = r2;
            *(H8*)(XT + (3 * 16 + pi) * LD + mh * 8) = r3;
            *(H8*)(XT + (4 * 16 + pi) * LD + mh * 8) = r4;
            if (pg + 1 < PGRPS && tid < 160) {
                const float4* src = (const float4*)(d_Wc2 + (size_t)(pg + 1) * 80 * 16
                                                    + (size_t)(tid >> 1) * 16 + (tid & 1) * 8);
                w2 = src[0];
            }
            __syncthreads();
            #pragma unroll
            for (int mf = 0; mf < 5; mf++) {
                wmma::fragment<wmma::matrix_a, 16, 16, 16, __half, wmma::col_major> a;
                wmma::fragment<wmma::matrix_b, 16, 16, 16, __half, wmma::row_major> b;
                wmma::load_matrix_sync(a, XT + (mf * 16) * LD + wrow, LD);
                wmma::load_matrix_sync(b, WB + (mf * 16) * W2_LD, W2_LD);
                wmma::mma_sync(acc2[mf], a, b, acc2[mf]);
            }
        }
        __syncthreads();   // all mma done before staging overwrites region C
        float* YS = (float*)(smem + C2_YS);
        #pragma unroll
        for (int m = 0; m < 5; m++)
            wmma::store_matrix_sync(YS + wrow + (m * 16) * YS_LD, acc2[m], YS_LD,
                                    wmma::mem_col_major);
        __syncthreads();
        for (int idx = tid; idx < CTA_M * 80; idx += THREADS) {
            int n = idx / 80, c = idx % 80;
            int m = c >> 4, r = c & 15;
            out[(size_t)(nodeBase + n) * DOUT + 160 + r * 5 + m] = YS[n + c * YS_LD];
        }
    }
}

// ================= launch =================
extern "C" void kernel_launch(void* const* d_in, const int* in_sizes, int n_in,
                              void* d_out, int out_size) {
    const float* feats = (const float*)d_in[0];
    const float* gates = (const float*)d_in[1];
    const float* Wss0  = (const float*)d_in[2];
    const float* Wsv1  = (const float*)d_in[3];
    const float* Wvv0  = (const float*)d_in[4];
    const float* Wvv2  = (const float*)d_in[5];
    float* out = (float*)d_out;

    static bool attr_set = false;
    if (!attr_set) {
        cudaFuncSetAttribute(nltsq_main, cudaFuncAttributeMaxDynamicSharedMemorySize, SMEM_TOTAL);
        attr_set = true;
    }

    prep_all<<<(N_ALL + 255) / 256, 256>>>(gates, Wss0, Wsv1, Wvv0, Wvv2);
    nltsq_main<<<NODES / CTA_M, THREADS, SMEM_TOTAL>>>(feats, out);
}